// round 9
// baseline (speedup 1.0000x reference)
#include <cuda_runtime.h>
#include <cuda_fp16.h>
#include <stdint.h>

// ---------------------------------------------------------------------------
// LightGCN: N=100000, D=64, E=1000000, 3 layers.
// out[0:ND] = E0 ; out[ND:2ND] = (E0 + x1 + x2 + x3)/4
//
// y = dinv (.) x stored fp16 (fp32 accumulation). Propagate = R6 shape:
// 8 lanes/node (uint4 = 16B fp16), 32 nodes/block, 2-edge unroll, fp32 FADD.
// NEW: nodes processed in degree-sorted order (64-bin bucket sort) so the 4
// node-groups in a warp have equal degree -> minimal max-of-4 divergence waste.
// ---------------------------------------------------------------------------

#define MAXN 100000
#define MAXE 1000000
#define D    64
#define NBIN 64

__device__ int     g_deg[MAXN];       // zero at load; re-zeroed in fill_init
__device__ float   g_dinv[MAXN];
__device__ float   g_rdi[MAXN];
__device__ int     g_off[MAXN + 1];
__device__ int     g_rank[MAXE];
__device__ int     g_order[MAXN];     // nodes sorted by degree bucket
__device__ int     g_dbin[NBIN];      // degree histogram
__device__ int     g_dbincur[NBIN];   // degree-bin cursors
__device__ int     g_blocksums[128];
__device__ int     g_scanflag[128];
__device__ int     g_src[MAXE];
__device__ uint4   g_y0[MAXN * 8];    // fp16 rows: 64 halfs = 8 uint4
__device__ uint4   g_y1[MAXN * 8];
__device__ uint4   g_y2[MAXN * 8];

// ---------------------------------------------------------------------------
__device__ __forceinline__ bool block_is64(const int* __restrict__ p, int* s_flag) {
    if (threadIdx.x == 0) {
        int nz = 0;
        #pragma unroll 8
        for (int j = 1; j < 256; j += 2) nz += (p[j] != 0);
        *s_flag = (nz == 0);
    }
    __syncthreads();
    return *s_flag != 0;
}

// Edge histogram (dst) + per-edge rank; block 0 resets small scratch.
__global__ void k_hist(const void* __restrict__ ei, int E) {
    __shared__ int s64;
    bool is64 = block_is64((const int*)ei, &s64);
    if (blockIdx.x == 0 && threadIdx.x < 128) {
        g_scanflag[threadIdx.x] = 0;
        if (threadIdx.x < NBIN) {
            g_dbin[threadIdx.x] = 0;
            g_dbincur[threadIdx.x] = 0;
        }
    }
    int base = (blockIdx.x * blockDim.x + threadIdx.x) * 4;
    if (base >= E) return;
    int d0, d1, d2, d3;
    int n = E - base;
    if (is64) {
        const long long* p = (const long long*)ei + E + base;
        if (n >= 4) {
            longlong2 a = ((const longlong2*)p)[0];
            longlong2 b = ((const longlong2*)p)[1];
            d0 = (int)a.x; d1 = (int)a.y; d2 = (int)b.x; d3 = (int)b.y;
        } else {
            d0 = (int)p[0];
            d1 = (n > 1) ? (int)p[1] : -1;
            d2 = (n > 2) ? (int)p[2] : -1;
            d3 = -1;
        }
    } else {
        const int* p = (const int*)ei + E + base;
        if (n >= 4) {
            int4 a = *(const int4*)p;
            d0 = a.x; d1 = a.y; d2 = a.z; d3 = a.w;
        } else {
            d0 = p[0];
            d1 = (n > 1) ? p[1] : -1;
            d2 = (n > 2) ? p[2] : -1;
            d3 = -1;
        }
    }
    int r0 = atomicAdd(&g_deg[d0], 1);
    int r1 = (d1 >= 0) ? atomicAdd(&g_deg[d1], 1) : 0;
    int r2 = (d2 >= 0) ? atomicAdd(&g_deg[d2], 1) : 0;
    int r3 = (d3 >= 0) ? atomicAdd(&g_deg[d3], 1) : 0;
    if (n >= 4) {
        int4 r; r.x = r0; r.y = r1; r.z = r2; r.w = r3;
        *(int4*)(g_rank + base) = r;
    } else {
        g_rank[base] = r0;
        if (n > 1) g_rank[base + 1] = r1;
        if (n > 2) g_rank[base + 2] = r2;
    }
}

// Single-pass exclusive scan of deg -> off (+ dinv/rdi + degree-bin histogram).
__global__ void k_scan(int N, int E) {
    __shared__ int sh[1024];
    int tid = threadIdx.x;
    int bid = blockIdx.x;
    int i = bid * 1024 + tid;
    int v = (i < N) ? g_deg[i] : 0;
    if (i < N) {
        float fv = (float)v;
        g_dinv[i] = (v > 0) ? rsqrtf(fv) : 0.0f;
        g_rdi[i]  = (v > 0) ? sqrtf(fv)  : 0.0f;
        int b = v < (NBIN - 1) ? v : (NBIN - 1);
        atomicAdd(&g_dbin[b], 1);
    }
    sh[tid] = v;
    __syncthreads();
    #pragma unroll
    for (int ofs = 1; ofs < 1024; ofs <<= 1) {
        int t = (tid >= ofs) ? sh[tid - ofs] : 0;
        __syncthreads();
        sh[tid] += t;
        __syncthreads();
    }
    int incl = sh[tid];
    if (tid == 1023) {
        g_blocksums[bid] = incl;
        __threadfence();
        ((volatile int*)g_scanflag)[bid] = 1;
    }
    __syncthreads();
    int part = 0;
    if (tid < bid) {
        while (((volatile int*)g_scanflag)[tid] == 0) {}
        __threadfence();
        part = g_blocksums[tid];
    }
    sh[tid] = part;
    __syncthreads();
    #pragma unroll
    for (int ofs = 512; ofs > 0; ofs >>= 1) {
        if (tid < ofs) sh[tid] += sh[tid + ofs];
        __syncthreads();
    }
    int base = sh[0];
    if (i < N) g_off[i] = base + incl - v;
    if (i == 0) g_off[N] = E;
}

// Fused: atomic-free CSR fill + y0/out init + degree-ordered node permutation
// (+ deg reset for graph replay).
__global__ void k_fill_init(const void* __restrict__ ei,
                            const float4* __restrict__ E0,
                            float4* __restrict__ out,
                            int E, int NQ, int N) {
    __shared__ int s64;
    __shared__ int binpref[NBIN];
    int tid = threadIdx.x;
    // Exclusive prefix of the (read-only) degree histogram, identical per block.
    int own = 0;
    if (tid < NBIN) { own = g_dbin[tid]; binpref[tid] = own; }
    bool is64 = block_is64((const int*)ei, &s64);  // includes a __syncthreads
    #pragma unroll
    for (int ofs = 1; ofs < NBIN; ofs <<= 1) {
        int t = (tid >= ofs && tid < NBIN) ? binpref[tid - ofs] : 0;
        __syncthreads();
        if (tid < NBIN) binpref[tid] += t;
        __syncthreads();
    }
    if (tid < NBIN) binpref[tid] -= own;  // exclusive
    __syncthreads();

    int i = blockIdx.x * blockDim.x + tid;
    if (i < N) {
        int dgi = g_deg[i];
        g_deg[i] = 0;
        int b = dgi < (NBIN - 1) ? dgi : (NBIN - 1);
        int pos = binpref[b] + atomicAdd(&g_dbincur[b], 1);
        g_order[pos] = i;
    }
    if (i < E) {
        int s, d;
        if (is64) {
            s = (int)((const long long*)ei)[i];
            d = (int)((const long long*)ei)[E + i];
        } else {
            s = ((const int*)ei)[i];
            d = ((const int*)ei)[E + i];
        }
        g_src[g_off[d] + g_rank[i]] = s;
    }
    if (i < NQ) {
        float4 v = E0[i];
        out[i] = v;
        float di = g_dinv[i >> 4];
        uint2 w;
        __half2* hw = (__half2*)&w;
        hw[0] = __floats2half2_rn(v.x * di, v.y * di);
        hw[1] = __floats2half2_rn(v.z * di, v.w * di);
        ((uint2*)g_y0)[i] = w;
    }
}

// R6-shape propagate: 8 lanes/node, 32 nodes/block, 2-edge unroll, fp32 accum.
// Nodes come via g_order so warps see equal degrees.
__global__ void k_propagate(const uint4* __restrict__ y, uint4* __restrict__ yn, int N) {
    int slot = blockIdx.x * 32 + threadIdx.y;
    if (slot >= N) return;
    int node = g_order[slot];
    int t = threadIdx.x;  // 0..7
    int beg = g_off[node];
    int end = g_off[node + 1];
    float s0[8] = {0, 0, 0, 0, 0, 0, 0, 0};
    float s1[8] = {0, 0, 0, 0, 0, 0, 0, 0};
    int e = beg;
    for (; e + 1 < end; e += 2) {
        int sa = g_src[e];
        int sb = g_src[e + 1];
        uint4 ua = y[sa * 8 + t];
        uint4 ub = y[sb * 8 + t];
        const __half2* ha = (const __half2*)&ua;
        const __half2* hb = (const __half2*)&ub;
        #pragma unroll
        for (int j = 0; j < 4; j++) {
            float2 fa = __half22float2(ha[j]);
            float2 fb = __half22float2(hb[j]);
            s0[2 * j] += fa.x; s0[2 * j + 1] += fa.y;
            s1[2 * j] += fb.x; s1[2 * j + 1] += fb.y;
        }
    }
    if (e < end) {
        uint4 ua = y[g_src[e] * 8 + t];
        const __half2* ha = (const __half2*)&ua;
        #pragma unroll
        for (int j = 0; j < 4; j++) {
            float2 fa = __half22float2(ha[j]);
            s0[2 * j] += fa.x; s0[2 * j + 1] += fa.y;
        }
    }
    float di2 = g_dinv[node];
    di2 *= di2;
    uint4 w;
    __half2* hw = (__half2*)&w;
    #pragma unroll
    for (int j = 0; j < 4; j++)
        hw[j] = __floats2half2_rn(di2 * (s0[2 * j] + s1[2 * j]),
                                  di2 * (s0[2 * j + 1] + s1[2 * j + 1]));
    yn[node * 8 + t] = w;
}

// Final layer fused with output: out = 0.25*(E0 + (y1+y2)*rdi + di*s3).
__global__ void k_propagate_last(const uint4* __restrict__ y2,
                                 const uint4* __restrict__ y1,
                                 const float4* __restrict__ E0,
                                 float4* __restrict__ out, int N, int NQ) {
    int slot = blockIdx.x * 32 + threadIdx.y;
    if (slot >= N) return;
    int node = g_order[slot];
    int t = threadIdx.x;
    int beg = g_off[node];
    int end = g_off[node + 1];
    float s0[8] = {0, 0, 0, 0, 0, 0, 0, 0};
    float s1[8] = {0, 0, 0, 0, 0, 0, 0, 0};
    int e = beg;
    for (; e + 1 < end; e += 2) {
        int sa = g_src[e];
        int sb = g_src[e + 1];
        uint4 ua = y2[sa * 8 + t];
        uint4 ub = y2[sb * 8 + t];
        const __half2* ha = (const __half2*)&ua;
        const __half2* hb = (const __half2*)&ub;
        #pragma unroll
        for (int j = 0; j < 4; j++) {
            float2 fa = __half22float2(ha[j]);
            float2 fb = __half22float2(hb[j]);
            s0[2 * j] += fa.x; s0[2 * j + 1] += fa.y;
            s1[2 * j] += fb.x; s1[2 * j + 1] += fb.y;
        }
    }
    if (e < end) {
        uint4 ua = y2[g_src[e] * 8 + t];
        const __half2* ha = (const __half2*)&ua;
        #pragma unroll
        for (int j = 0; j < 4; j++) {
            float2 fa = __half22float2(ha[j]);
            s0[2 * j] += fa.x; s0[2 * j + 1] += fa.y;
        }
    }
    float di  = g_dinv[node];
    float rdi = g_rdi[node];

    uint4 u1 = y1[node * 8 + t];
    uint4 u2 = y2[node * 8 + t];
    const __half2* h1 = (const __half2*)&u1;
    const __half2* h2 = (const __half2*)&u2;

    float r[8];
    #pragma unroll
    for (int j = 0; j < 4; j++) {
        float2 g1 = __half22float2(h1[j]);
        float2 g2 = __half22float2(h2[j]);
        r[2 * j]     = rdi * (g1.x + g2.x) + di * (s0[2 * j]     + s1[2 * j]);
        r[2 * j + 1] = rdi * (g1.y + g2.y) + di * (s0[2 * j + 1] + s1[2 * j + 1]);
    }

    int o4 = node * 16 + t * 2;
    float4 e0a = E0[o4], e0b = E0[o4 + 1];
    float4 r0, r1;
    r0.x = 0.25f * (e0a.x + r[0]);
    r0.y = 0.25f * (e0a.y + r[1]);
    r0.z = 0.25f * (e0a.z + r[2]);
    r0.w = 0.25f * (e0a.w + r[3]);
    r1.x = 0.25f * (e0b.x + r[4]);
    r1.y = 0.25f * (e0b.y + r[5]);
    r1.z = 0.25f * (e0b.z + r[6]);
    r1.w = 0.25f * (e0b.w + r[7]);
    out[NQ + o4] = r0;
    out[NQ + o4 + 1] = r1;
}

// ---------------------------------------------------------------------------

extern "C" void kernel_launch(void* const* d_in, const int* in_sizes, int n_in,
                              void* d_out, int out_size) {
    const float4* E0 = (const float4*)d_in[0];
    const void*   ei = d_in[1];
    float4*       out = (float4*)d_out;

    int N  = in_sizes[0] / D;   // 100000
    int E  = in_sizes[1] / 2;   // 1000000
    int NQ = N * 16;

    void *p0 = nullptr, *p1 = nullptr, *p2 = nullptr;
    cudaGetSymbolAddress(&p0, g_y0);
    cudaGetSymbolAddress(&p1, g_y1);
    cudaGetSymbolAddress(&p2, g_y2);
    uint4* y0 = (uint4*)p0;
    uint4* y1 = (uint4*)p1;
    uint4* y2 = (uint4*)p2;

    const int T = 256;
    int nb_scan = (N + 1023) / 1024;
    int nb_hist = ((E + 3) / 4 + T - 1) / T;

    k_hist<<<nb_hist, T>>>(ei, E);
    k_scan<<<nb_scan, 1024>>>(N, E);
    k_fill_init<<<(NQ + T - 1) / T, T>>>(ei, E0, out, E, NQ, N);

    dim3 pb(8, 32);
    int  pg = (N + 31) / 32;
    k_propagate<<<pg, pb>>>(y0, y1, N);
    k_propagate<<<pg, pb>>>(y1, y2, N);
    k_propagate_last<<<pg, pb>>>(y2, y1, E0, out, N, NQ);
}

// round 10
// speedup vs baseline: 1.4148x; 1.4148x over previous
#include <cuda_runtime.h>
#include <cuda_fp16.h>
#include <stdint.h>

// ---------------------------------------------------------------------------
// LightGCN: N=100000, D=64, E=1000000, 3 layers.
// out[0:ND] = E0 ; out[ND:2ND] = (E0 + x1 + x2 + x3)/4
//
// y = dinv (.) x stored fp16; x_l = di*s_l, y_l = di^2*s_l, s_l = sum y_{l-1}[src].
// Base = R6 (best measured, 110.6us). Only change: mid-layer propagate uses
// HADD2 2-bank accumulation + __launch_bounds__(256,8) -> 32 regs, 64 warps/SM
// (was 40 regs / 48 warps): more latency hiding AND fewer issue slots per edge.
// ---------------------------------------------------------------------------

#define MAXN 100000
#define MAXE 1000000
#define D    64

__device__ int    g_deg[MAXN];        // zero at load; re-zeroed in fill_init
__device__ float  g_dinv[MAXN];
__device__ float  g_rdi[MAXN];
__device__ int    g_off[MAXN + 1];
__device__ int    g_cursor[MAXN];
__device__ int    g_blocksums[128];
__device__ int    g_scanflag[128];
__device__ int    g_src[MAXE];
__device__ uint4  g_y0[MAXN * 8];
__device__ uint4  g_y1[MAXN * 8];
__device__ uint4  g_y2[MAXN * 8];

// ---------------------------------------------------------------------------
// Per-block dtype sniff: int64 indices < 2^31 have every odd 32-bit word == 0.
__device__ __forceinline__ bool block_is64(const int* __restrict__ p, int* s_flag) {
    if (threadIdx.x == 0) {
        int nz = 0;
        #pragma unroll 8
        for (int j = 1; j < 256; j += 2) nz += (p[j] != 0);
        *s_flag = (nz == 0);
    }
    __syncthreads();
    return *s_flag != 0;
}

// Histogram of destinations, 4 edges per thread. Block 0 also resets scan flags.
__global__ void k_hist(const void* __restrict__ ei, int E) {
    __shared__ int s64;
    bool is64 = block_is64((const int*)ei, &s64);
    if (blockIdx.x == 0 && threadIdx.x < 128) g_scanflag[threadIdx.x] = 0;
    int base = (blockIdx.x * blockDim.x + threadIdx.x) * 4;
    if (base >= E) return;
    int d0, d1, d2, d3;
    int n = E - base;
    if (is64) {
        const long long* p = (const long long*)ei + E + base;
        if (n >= 4) {
            longlong2 a = ((const longlong2*)p)[0];
            longlong2 b = ((const longlong2*)p)[1];
            d0 = (int)a.x; d1 = (int)a.y; d2 = (int)b.x; d3 = (int)b.y;
        } else {
            d0 = (int)p[0];
            d1 = (n > 1) ? (int)p[1] : -1;
            d2 = (n > 2) ? (int)p[2] : -1;
            d3 = -1;
        }
    } else {
        const int* p = (const int*)ei + E + base;
        if (n >= 4) {
            int4 a = *(const int4*)p;
            d0 = a.x; d1 = a.y; d2 = a.z; d3 = a.w;
        } else {
            d0 = p[0];
            d1 = (n > 1) ? p[1] : -1;
            d2 = (n > 2) ? p[2] : -1;
            d3 = -1;
        }
    }
    atomicAdd(&g_deg[d0], 1);
    if (d1 >= 0) atomicAdd(&g_deg[d1], 1);
    if (d2 >= 0) atomicAdd(&g_deg[d2], 1);
    if (d3 >= 0) atomicAdd(&g_deg[d3], 1);
}

// Single-pass exclusive scan of deg -> off (+ dinv/rdi). All 98 blocks resident.
__global__ void k_scan(int N, int E) {
    __shared__ int sh[1024];
    int tid = threadIdx.x;
    int bid = blockIdx.x;
    int i = bid * 1024 + tid;
    int v = (i < N) ? g_deg[i] : 0;
    if (i < N) {
        float fv = (float)v;
        g_dinv[i] = (v > 0) ? rsqrtf(fv) : 0.0f;
        g_rdi[i]  = (v > 0) ? sqrtf(fv)  : 0.0f;
    }
    sh[tid] = v;
    __syncthreads();
    #pragma unroll
    for (int ofs = 1; ofs < 1024; ofs <<= 1) {
        int t = (tid >= ofs) ? sh[tid - ofs] : 0;
        __syncthreads();
        sh[tid] += t;
        __syncthreads();
    }
    int incl = sh[tid];
    if (tid == 1023) {
        g_blocksums[bid] = incl;
        __threadfence();
        ((volatile int*)g_scanflag)[bid] = 1;
    }
    __syncthreads();
    int part = 0;
    if (tid < bid) {
        while (((volatile int*)g_scanflag)[tid] == 0) {}
        __threadfence();
        part = g_blocksums[tid];
    }
    sh[tid] = part;
    __syncthreads();
    #pragma unroll
    for (int ofs = 512; ofs > 0; ofs >>= 1) {
        if (tid < ofs) sh[tid] += sh[tid + ofs];
        __syncthreads();
    }
    int base = sh[0];
    if (i < N) {
        int o = base + incl - v;
        g_off[i] = o;
        g_cursor[i] = o;
    }
    if (i == 0) g_off[N] = E;
}

// Fused: CSR fill (atomic cursor) + y0/out init + deg reset.
__global__ void k_fill_init(const void* __restrict__ ei,
                            const float4* __restrict__ E0,
                            float4* __restrict__ out,
                            int E, int NQ, int N) {
    __shared__ int s64;
    bool is64 = block_is64((const int*)ei, &s64);
    int i = blockIdx.x * blockDim.x + threadIdx.x;
    if (i < N) g_deg[i] = 0;
    if (i < E) {
        int s, d;
        if (is64) {
            s = (int)((const long long*)ei)[i];
            d = (int)((const long long*)ei)[E + i];
        } else {
            s = ((const int*)ei)[i];
            d = ((const int*)ei)[E + i];
        }
        int pos = atomicAdd(&g_cursor[d], 1);
        g_src[pos] = s;
    }
    if (i < NQ) {
        float4 v = E0[i];
        out[i] = v;
        float di = g_dinv[i >> 4];
        uint2 w;
        __half2* hw = (__half2*)&w;
        hw[0] = __floats2half2_rn(v.x * di, v.y * di);
        hw[1] = __floats2half2_rn(v.z * di, v.w * di);
        ((uint2*)g_y0)[i] = w;
    }
}

// Mid-layer propagate: 8 lanes/node, 32 nodes/block, 2-edge unroll.
// HADD2 2-bank accumulation (8 half2 regs) + forced 8 blocks/SM (64 warps).
__global__ void __launch_bounds__(256, 8)
k_propagate(const uint4* __restrict__ y, uint4* __restrict__ yn, int N) {
    int node = blockIdx.x * 32 + threadIdx.y;
    if (node >= N) return;
    int t = threadIdx.x;  // 0..7
    int beg = g_off[node];
    int end = g_off[node + 1];
    __half2 z = __float2half2_rn(0.f);
    __half2 a0[4] = {z, z, z, z};
    __half2 a1[4] = {z, z, z, z};
    int e = beg;
    for (; e + 1 < end; e += 2) {
        int sa = g_src[e];
        int sb = g_src[e + 1];
        uint4 ua = y[sa * 8 + t];
        uint4 ub = y[sb * 8 + t];
        const __half2* ha = (const __half2*)&ua;
        const __half2* hb = (const __half2*)&ub;
        #pragma unroll
        for (int j = 0; j < 4; j++) {
            a0[j] = __hadd2(a0[j], ha[j]);
            a1[j] = __hadd2(a1[j], hb[j]);
        }
    }
    if (e < end) {
        uint4 ua = y[g_src[e] * 8 + t];
        const __half2* ha = (const __half2*)&ua;
        #pragma unroll
        for (int j = 0; j < 4; j++) a0[j] = __hadd2(a0[j], ha[j]);
    }
    float di2 = g_dinv[node];
    di2 *= di2;
    uint4 w;
    __half2* hw = (__half2*)&w;
    #pragma unroll
    for (int j = 0; j < 4; j++) {
        float2 f0 = __half22float2(a0[j]);
        float2 f1 = __half22float2(a1[j]);
        hw[j] = __floats2half2_rn(di2 * (f0.x + f1.x), di2 * (f0.y + f1.y));
    }
    yn[node * 8 + t] = w;
}

// Final layer fused with output (unchanged from R6, fp32 accumulation):
// out = 0.25*(E0 + (y1+y2)*rdi + di*s3).
__global__ void k_propagate_last(const uint4* __restrict__ y2,
                                 const uint4* __restrict__ y1,
                                 const float4* __restrict__ E0,
                                 float4* __restrict__ out, int N, int NQ) {
    int node = blockIdx.x * 32 + threadIdx.y;
    if (node >= N) return;
    int t = threadIdx.x;
    int beg = g_off[node];
    int end = g_off[node + 1];
    float s0[8] = {0, 0, 0, 0, 0, 0, 0, 0};
    float s1[8] = {0, 0, 0, 0, 0, 0, 0, 0};
    int e = beg;
    for (; e + 1 < end; e += 2) {
        int sa = g_src[e];
        int sb = g_src[e + 1];
        uint4 ua = y2[sa * 8 + t];
        uint4 ub = y2[sb * 8 + t];
        const __half2* ha = (const __half2*)&ua;
        const __half2* hb = (const __half2*)&ub;
        #pragma unroll
        for (int j = 0; j < 4; j++) {
            float2 fa = __half22float2(ha[j]);
            float2 fb = __half22float2(hb[j]);
            s0[2 * j] += fa.x; s0[2 * j + 1] += fa.y;
            s1[2 * j] += fb.x; s1[2 * j + 1] += fb.y;
        }
    }
    if (e < end) {
        uint4 ua = y2[g_src[e] * 8 + t];
        const __half2* ha = (const __half2*)&ua;
        #pragma unroll
        for (int j = 0; j < 4; j++) {
            float2 fa = __half22float2(ha[j]);
            s0[2 * j] += fa.x; s0[2 * j + 1] += fa.y;
        }
    }
    float di  = g_dinv[node];
    float rdi = g_rdi[node];

    uint4 u1 = y1[node * 8 + t];
    uint4 u2 = y2[node * 8 + t];
    const __half2* h1 = (const __half2*)&u1;
    const __half2* h2 = (const __half2*)&u2;

    float r[8];
    #pragma unroll
    for (int j = 0; j < 4; j++) {
        float2 g1 = __half22float2(h1[j]);
        float2 g2 = __half22float2(h2[j]);
        r[2 * j]     = rdi * (g1.x + g2.x) + di * (s0[2 * j]     + s1[2 * j]);
        r[2 * j + 1] = rdi * (g1.y + g2.y) + di * (s0[2 * j + 1] + s1[2 * j + 1]);
    }

    int o4 = node * 16 + t * 2;
    float4 e0a = E0[o4], e0b = E0[o4 + 1];
    float4 r0, r1;
    r0.x = 0.25f * (e0a.x + r[0]);
    r0.y = 0.25f * (e0a.y + r[1]);
    r0.z = 0.25f * (e0a.z + r[2]);
    r0.w = 0.25f * (e0a.w + r[3]);
    r1.x = 0.25f * (e0b.x + r[4]);
    r1.y = 0.25f * (e0b.y + r[5]);
    r1.z = 0.25f * (e0b.z + r[6]);
    r1.w = 0.25f * (e0b.w + r[7]);
    out[NQ + o4] = r0;
    out[NQ + o4 + 1] = r1;
}

// ---------------------------------------------------------------------------

extern "C" void kernel_launch(void* const* d_in, const int* in_sizes, int n_in,
                              void* d_out, int out_size) {
    const float4* E0 = (const float4*)d_in[0];
    const void*   ei = d_in[1];
    float4*       out = (float4*)d_out;

    int N  = in_sizes[0] / D;   // 100000
    int E  = in_sizes[1] / 2;   // 1000000
    int NQ = N * 16;

    void *p0 = nullptr, *p1 = nullptr, *p2 = nullptr;
    cudaGetSymbolAddress(&p0, g_y0);
    cudaGetSymbolAddress(&p1, g_y1);
    cudaGetSymbolAddress(&p2, g_y2);
    uint4* y0 = (uint4*)p0;
    uint4* y1 = (uint4*)p1;
    uint4* y2 = (uint4*)p2;

    const int T = 256;
    int nb_scan = (N + 1023) / 1024;
    int nb_hist = ((E + 3) / 4 + T - 1) / T;

    k_hist<<<nb_hist, T>>>(ei, E);
    k_scan<<<nb_scan, 1024>>>(N, E);
    k_fill_init<<<(NQ + T - 1) / T, T>>>(ei, E0, out, E, NQ, N);

    dim3 pb(8, 32);
    int  pg = (N + 31) / 32;
    k_propagate<<<pg, pb>>>(y0, y1, N);
    k_propagate<<<pg, pb>>>(y1, y2, N);
    k_propagate_last<<<pg, pb>>>(y2, y1, E0, out, N, NQ);
}